// round 17
// baseline (speedup 1.0000x reference)
#include <cuda_runtime.h>
#include <cuda_fp16.h>
#include <math.h>
#include <stdint.h>

#define TT 2048
#define HH 1024
#define FF 2816
#define NE 8
#define BM 128
#define BN 64       // gateup N per operand
#define DBN 128     // down N tile
#define BKH 64      // k per pipeline stage
#define ASTR 72     // halves per smem row (64 + 8 pad)

#define NMB   (TT / BM)          // 16 m-blocks per expert
#define NFT   (FF / BN)          // 44 gateup f-tiles
#define NGT   (HH / DBN)         // 8 down n-tiles
#define NGUE  (NFT * NMB)        // 704 gateup blocks per expert
#define NDNE  (NGT * NMB)        // 128 down blocks per expert
#define SEG   (NGUE + NDNE)      // 832 blocks per expert segment

// ---------------- scratch ----------------
__device__ int    g_cnt[NE];
__device__ int    g_rdy[NE * NMB];   // per-(e,mb) gateup completion counters
__device__ int    g_tok[NE * TT];
__device__ float  g_wgt[NE * TT];
__device__ __half g_xh[(size_t)NE * TT * HH];
__device__ __half g_hh[(size_t)NE * TT * FF];

// ---------------- helpers ----------------
__device__ __forceinline__ uint32_t smem_u32(const void* p) {
    uint32_t a;
    asm("{ .reg .u64 t; cvta.to.shared.u64 t, %1; cvt.u32.u64 %0, t; }" : "=r"(a) : "l"(p));
    return a;
}
__device__ __forceinline__ void ldsm4(uint32_t* r, uint32_t a) {
    asm volatile("ldmatrix.sync.aligned.m8n8.x4.shared.b16 {%0,%1,%2,%3}, [%4];"
        : "=r"(r[0]), "=r"(r[1]), "=r"(r[2]), "=r"(r[3]) : "r"(a));
}
__device__ __forceinline__ void mma16816(float* d, const uint32_t* a, const uint32_t* b) {
    asm volatile("mma.sync.aligned.m16n8k16.row.col.f32.f16.f16.f32 "
        "{%0,%1,%2,%3}, {%4,%5,%6,%7}, {%8,%9}, {%0,%1,%2,%3};"
        : "+f"(d[0]), "+f"(d[1]), "+f"(d[2]), "+f"(d[3])
        : "r"(a[0]), "r"(a[1]), "r"(a[2]), "r"(a[3]), "r"(b[0]), "r"(b[1]));
}
__device__ __forceinline__ void cp16(uint32_t d, const void* s) {
    asm volatile("cp.async.ca.shared.global [%0], [%1], 16;" :: "r"(d), "l"(s));
}
#define CP_COMMIT() asm volatile("cp.async.commit_group;" ::: "memory")
#define CP_WAIT()   asm volatile("cp.async.wait_group 0;" ::: "memory")

__device__ __forceinline__ void sts8(__half* dst, float4 a, float4 b) {
    __half2 h0 = __floats2half2_rn(a.x, a.y);
    __half2 h1 = __floats2half2_rn(a.z, a.w);
    __half2 h2 = __floats2half2_rn(b.x, b.y);
    __half2 h3 = __floats2half2_rn(b.z, b.w);
    uint4 v;
    v.x = *(uint32_t*)&h0; v.y = *(uint32_t*)&h1;
    v.z = *(uint32_t*)&h2; v.w = *(uint32_t*)&h3;
    *(uint4*)dst = v;
}

// ---------------- router + gather fused ----------------
__global__ void router_gather(const float* __restrict__ x, const float* __restrict__ Wgate) {
    int warp = (blockIdx.x * blockDim.x + threadIdx.x) >> 5;
    int lane = threadIdx.x & 31;
    if (warp >= TT) return;
    const float* xt = x + (size_t)warp * HH;
    float acc[NE];
#pragma unroll
    for (int e = 0; e < NE; e++) acc[e] = 0.f;
    for (int k = lane; k < HH; k += 32) {
        float xv = xt[k];
#pragma unroll
        for (int e = 0; e < NE; e++) acc[e] += xv * Wgate[e * HH + k];
    }
#pragma unroll
    for (int off = 16; off > 0; off >>= 1) {
#pragma unroll
        for (int e = 0; e < NE; e++) acc[e] += __shfl_xor_sync(0xffffffffu, acc[e], off);
    }
    int i0 = 0, i1 = 0, p0 = 0, p1 = 0;
    if (lane == 0) {
        float l0 = acc[0];
#pragma unroll
        for (int e = 1; e < NE; e++) if (acc[e] > l0) { l0 = acc[e]; i0 = e; }
        float l1 = -INFINITY; i1 = -1;
#pragma unroll
        for (int e = 0; e < NE; e++) if (e != i0 && acc[e] > l1) { l1 = acc[e]; i1 = e; }
        float w0 = 1.f / (1.f + expf(l1 - l0));
        float w1 = 1.f - w0;
        p0 = atomicAdd(&g_cnt[i0], 1);
        g_tok[i0 * TT + p0] = warp; g_wgt[i0 * TT + p0] = w0;
        p1 = atomicAdd(&g_cnt[i1], 1);
        g_tok[i1 * TT + p1] = warp; g_wgt[i1 * TT + p1] = w1;
    }
    i0 = __shfl_sync(0xffffffffu, i0, 0); p0 = __shfl_sync(0xffffffffu, p0, 0);
    i1 = __shfl_sync(0xffffffffu, i1, 0); p1 = __shfl_sync(0xffffffffu, p1, 0);
    const float4* src = (const float4*)xt;
    __half2* d0 = (__half2*)(g_xh + ((size_t)i0 * TT + p0) * HH);
    __half2* d1 = (__half2*)(g_xh + ((size_t)i1 * TT + p1) * HH);
#pragma unroll
    for (int q = 0; q < HH / 128; q++) {
        float4 v = src[lane + q * 32];
        __half2 a = __floats2half2_rn(v.x, v.y);
        __half2 b = __floats2half2_rn(v.z, v.w);
        int idx = (lane + q * 32) * 2;
        d0[idx] = a; d0[idx + 1] = b;
        d1[idx] = a; d1[idx + 1] = b;
    }
}

// ---------------- fused MoE, expert-interleaved dispatch ----------------
// Per-expert segment of SEG blocks: [0,NGUE) gateup roles, [NGUE,SEG) down roles.
// Linear dispatch order => every down block's producers precede it. No deadlock.
__global__ __launch_bounds__(256, 2) void moe_fused(const float* __restrict__ Wg,
                                                    const float* __restrict__ Wu,
                                                    const float* __restrict__ Wd,
                                                    float* __restrict__ out) {
    extern __shared__ __half sh[];
    int tid = threadIdx.x, lane = tid & 31, wid = tid >> 5;
    int wm = wid >> 2, wn = wid & 3;
    uint32_t sb = smem_u32(sh);
    int seg = lane >> 3, li = lane & 7;

    int e = blockIdx.x / SEG;
    int r = blockIdx.x % SEG;

    if (r < NGUE) {
        // ================= GATEUP ROLE =================
        const int STG = (BM + 2 * BN) * ASTR;
        int ft = r >> 4, mb = r & (NMB - 1);
        int n  = g_cnt[e];
        int m0 = mb * BM, n0 = ft * BN;
        if (m0 >= n) {
            if (tid == 0) atomicAdd(&g_rdy[e * NMB + mb], 1);
            return;
        }

        const __half* xab = g_xh + (size_t)e * TT * HH;
        const float*  wgb = Wg + (size_t)e * FF * HH;
        const float*  wub = Wu + (size_t)e * FF * HH;

        const __half* asrc[4]; uint32_t adst[4];
#pragma unroll
        for (int i = 0; i < 4; i++) {
            int ch = tid + i * 256, rr = ch >> 3, c = ch & 7;
            int rc = m0 + rr; if (rc >= n) rc = n - 1;
            asrc[i] = xab + (size_t)rc * HH + c * 8;
            adst[i] = sb + (rr * ASTR + c * 8) * 2;
        }
        int brow = tid >> 2, bc = tid & 3;
        const float* gsrc = wgb + (size_t)(n0 + brow) * HH + bc * 8;
        const float* usrc = wub + (size_t)(n0 + brow) * HH + bc * 8;
        __half* bgst = sh + BM * ASTR + brow * ASTR + bc * 8;
        __half* bust = bgst + BN * ASTR;

        uint32_t aA[4], aG, aU;
#pragma unroll
        for (int i = 0; i < 4; i++) {
            int row = wm * 64 + i * 16 + li + (seg & 1) * 8;
            aA[i] = sb + (row * ASTR + (seg >> 1) * 8) * 2;
        }
        {
            int row = wn * 16 + li + (seg >> 1) * 8;
            aG = sb + (BM * ASTR + row * ASTR + (seg & 1) * 8) * 2;
            aU = aG + BN * ASTR * 2;
        }

        float accg[4][2][4] = {}, accu[4][2][4] = {};
        float4 vg0, vg1, vu0, vu1;

#pragma unroll
        for (int i = 0; i < 4; i++) cp16(adst[i], asrc[i]);
        CP_COMMIT();
        vg0 = *(const float4*)gsrc; vg1 = *(const float4*)(gsrc + 4);
        vu0 = *(const float4*)usrc; vu1 = *(const float4*)(usrc + 4);
        sts8(bgst, vg0, vg1); sts8(bust, vu0, vu1);
        vg0 = *(const float4*)(gsrc + 32); vg1 = *(const float4*)(gsrc + 36);
        vu0 = *(const float4*)(usrc + 32); vu1 = *(const float4*)(usrc + 36);
        sts8(bgst + 32, vg0, vg1); sts8(bust + 32, vu0, vu1);
        CP_WAIT();
        __syncthreads();

        const int KT = HH / BKH;  // 16
        for (int kt = 0; kt < KT; kt++) {
            int cur = kt & 1;
            uint32_t so = (uint32_t)(cur * STG * 2);
            uint32_t po = (uint32_t)((cur ^ 1) * STG * 2);
            bool more = (kt + 1 < KT);
            int pk = (kt + 1) * BKH;
            if (more) {
#pragma unroll
                for (int i = 0; i < 4; i++) cp16(adst[i] + po, asrc[i] + pk);
                CP_COMMIT();
                vg0 = *(const float4*)(gsrc + pk); vg1 = *(const float4*)(gsrc + pk + 4);
                vu0 = *(const float4*)(usrc + pk); vu1 = *(const float4*)(usrc + pk + 4);
            }
#pragma unroll
            for (int ks = 0; ks < 2; ks++) {
                uint32_t af[4][4], bg[4], bu[4];
                ldsm4(bg, aG + so + ks * 32);
                ldsm4(bu, aU + so + ks * 32);
#pragma unroll
                for (int i = 0; i < 4; i++) ldsm4(af[i], aA[i] + so + ks * 32);
#pragma unroll
                for (int i = 0; i < 4; i++)
#pragma unroll
                    for (int j = 0; j < 2; j++) {
                        mma16816(accg[i][j], af[i], &bg[j * 2]);
                        mma16816(accu[i][j], af[i], &bu[j * 2]);
                    }
            }
            if (more) {
                __half* bo = bgst + (cur ^ 1) * STG;
                sts8(bo, vg0, vg1);
                sts8(bo + BN * ASTR, vu0, vu1);
                vg0 = *(const float4*)(gsrc + pk + 32); vg1 = *(const float4*)(gsrc + pk + 36);
                vu0 = *(const float4*)(usrc + pk + 32); vu1 = *(const float4*)(usrc + pk + 36);
            }
#pragma unroll
            for (int ks = 2; ks < 4; ks++) {
                uint32_t af[4][4], bg[4], bu[4];
                ldsm4(bg, aG + so + ks * 32);
                ldsm4(bu, aU + so + ks * 32);
#pragma unroll
                for (int i = 0; i < 4; i++) ldsm4(af[i], aA[i] + so + ks * 32);
#pragma unroll
                for (int i = 0; i < 4; i++)
#pragma unroll
                    for (int j = 0; j < 2; j++) {
                        mma16816(accg[i][j], af[i], &bg[j * 2]);
                        mma16816(accu[i][j], af[i], &bu[j * 2]);
                    }
            }
            if (more) {
                __half* bo = bgst + (cur ^ 1) * STG;
                sts8(bo + 32, vg0, vg1);
                sts8(bo + BN * ASTR + 32, vu0, vu1);
                CP_WAIT();
            }
            __syncthreads();
        }

        // epilogue: SwiGLU -> fp16 g_hh
#pragma unroll
        for (int i = 0; i < 4; i++) {
            int row0 = m0 + wm * 64 + i * 16 + (lane >> 2);
            int row1 = row0 + 8;
#pragma unroll
            for (int j = 0; j < 2; j++) {
                int col = n0 + wn * 16 + j * 8 + (lane & 3) * 2;
                if (row0 < n) {
                    float a0 = accg[i][j][0], a1 = accg[i][j][1];
                    float h0 = (a0 / (1.f + __expf(-a0))) * accu[i][j][0];
                    float h1 = (a1 / (1.f + __expf(-a1))) * accu[i][j][1];
                    *(__half2*)(g_hh + ((size_t)e * TT + row0) * FF + col) = __floats2half2_rn(h0, h1);
                }
                if (row1 < n) {
                    float a2 = accg[i][j][2], a3 = accg[i][j][3];
                    float h2 = (a2 / (1.f + __expf(-a2))) * accu[i][j][2];
                    float h3 = (a3 / (1.f + __expf(-a3))) * accu[i][j][3];
                    *(__half2*)(g_hh + ((size_t)e * TT + row1) * FF + col) = __floats2half2_rn(h2, h3);
                }
            }
        }
        // publish: all threads fence their g_hh stores, then one flag increment
        __threadfence();
        __syncthreads();
        if (tid == 0) atomicAdd(&g_rdy[e * NMB + mb], 1);

    } else {
        // ================= DOWN ROLE =================
        const int STG = (BM + DBN) * ASTR;
        int r2 = r - NGUE;
        int nt = r2 >> 4, mb = r2 & (NMB - 1);
        int n  = g_cnt[e];
        int m0 = mb * BM, n0 = nt * DBN;
        if (m0 >= n) return;

        const __half* hab = g_hh + (size_t)e * TT * FF;
        const float*  wdb = Wd + (size_t)e * HH * FF;

        const __half* asrc[4]; uint32_t adst[4];
#pragma unroll
        for (int i = 0; i < 4; i++) {
            int ch = tid + i * 256, rr = ch >> 3, c = ch & 7;
            int rc = m0 + rr; if (rc >= n) rc = n - 1;
            asrc[i] = hab + (size_t)rc * FF + c * 8;
            adst[i] = sb + (rr * ASTR + c * 8) * 2;
        }
        const float* bsrc[2]; __half* bst[2];
#pragma unroll
        for (int i = 0; i < 2; i++) {
            int task = tid + i * 256, rr = task >> 2, c = task & 3;
            bsrc[i] = wdb + (size_t)(n0 + rr) * FF + c * 8;
            bst[i] = sh + BM * ASTR + rr * ASTR + c * 8;
        }

        uint32_t aA[4], aB[2];
#pragma unroll
        for (int i = 0; i < 4; i++) {
            int row = wm * 64 + i * 16 + li + (seg & 1) * 8;
            aA[i] = sb + (row * ASTR + (seg >> 1) * 8) * 2;
        }
#pragma unroll
        for (int jj = 0; jj < 2; jj++) {
            int row = wn * 32 + jj * 16 + li + (seg >> 1) * 8;
            aB[jj] = sb + (BM * ASTR + row * ASTR + (seg & 1) * 8) * 2;
        }

        float acc[4][4][4] = {};
        float4 vb[2][2];

        // prefetch B stage 0 FULLY (cols 0..63) BEFORE the wait
#pragma unroll
        for (int i = 0; i < 2; i++) {
            float4 b0 = *(const float4*)(bsrc[i]);
            float4 b1 = *(const float4*)(bsrc[i] + 4);
            sts8(bst[i], b0, b1);
            b0 = *(const float4*)(bsrc[i] + 32);
            b1 = *(const float4*)(bsrc[i] + 36);
            sts8(bst[i] + 32, b0, b1);
        }

        // wait for all 44 gateup f-tiles of (e, mb)
        if (tid == 0) {
            while (atomicAdd(&g_rdy[e * NMB + mb], 0) < NFT) __nanosleep(256);
            __threadfence();
        }
        __syncthreads();

        // A prologue (stage 0, both half-k sets)
#pragma unroll
        for (int i = 0; i < 4; i++) cp16(adst[i], asrc[i]);
        CP_COMMIT();
        CP_WAIT();
        __syncthreads();

        const int KT = FF / BKH;  // 44
        for (int kt = 0; kt < KT; kt++) {
            int cur = kt & 1;
            uint32_t so = (uint32_t)(cur * STG * 2);
            uint32_t po = (uint32_t)((cur ^ 1) * STG * 2);
            bool more = (kt + 1 < KT);
            int pk = (kt + 1) * BKH;
            if (more) {
#pragma unroll
                for (int i = 0; i < 4; i++) cp16(adst[i] + po, asrc[i] + pk);
                CP_COMMIT();
#pragma unroll
                for (int i = 0; i < 2; i++) {
                    vb[i][0] = *(const float4*)(bsrc[i] + pk);
                    vb[i][1] = *(const float4*)(bsrc[i] + pk + 4);
                }
            }
#pragma unroll
            for (int ks = 0; ks < 2; ks++) {
                uint32_t af[4][4], bf[8];
                ldsm4(&bf[0], aB[0] + so + ks * 32);
                ldsm4(&bf[4], aB[1] + so + ks * 32);
#pragma unroll
                for (int i = 0; i < 4; i++) ldsm4(af[i], aA[i] + so + ks * 32);
#pragma unroll
                for (int i = 0; i < 4; i++)
#pragma unroll
                    for (int jj = 0; jj < 4; jj++) mma16816(acc[i][jj], af[i], &bf[jj * 2]);
            }
            if (more) {
                sts8(bst[0] + (cur ^ 1) * STG, vb[0][0], vb[0][1]);
                sts8(bst[1] + (cur ^ 1) * STG, vb[1][0], vb[1][1]);
#pragma unroll
                for (int i = 0; i < 2; i++) {
                    vb[i][0] = *(const float4*)(bsrc[i] + pk + 32);
                    vb[i][1] = *(const float4*)(bsrc[i] + pk + 36);
                }
            }
#pragma unroll
            for (int ks = 2; ks < 4; ks++) {
                uint32_t af[4][4], bf[8];
                ldsm4(&bf[0], aB[0] + so + ks * 32);
                ldsm4(&bf[4], aB[1] + so + ks * 32);
#pragma unroll
                for (int i = 0; i < 4; i++) ldsm4(af[i], aA[i] + so + ks * 32);
#pragma unroll
                for (int i = 0; i < 4; i++)
#pragma unroll
                    for (int jj = 0; jj < 4; jj++) mma16816(acc[i][jj], af[i], &bf[jj * 2]);
            }
            if (more) {
                sts8(bst[0] + (cur ^ 1) * STG + 32, vb[0][0], vb[0][1]);
                sts8(bst[1] + (cur ^ 1) * STG + 32, vb[1][0], vb[1][1]);
                CP_WAIT();
            }
            __syncthreads();
        }

        // epilogue: scale + atomicAdd into out
#pragma unroll
        for (int i = 0; i < 4; i++) {
            int row0 = m0 + wm * 64 + i * 16 + (lane >> 2);
            int row1 = row0 + 8;
            bool v0 = row0 < n, v1 = row1 < n;
            int t0 = 0; float w0 = 0.f;
            if (v0) { t0 = g_tok[e * TT + row0]; w0 = g_wgt[e * TT + row0]; }
            int t1 = 0; float w1 = 0.f;
            if (v1) { t1 = g_tok[e * TT + row1]; w1 = g_wgt[e * TT + row1]; }
#pragma unroll
            for (int jj = 0; jj < 4; jj++) {
                int col = n0 + wn * 32 + jj * 8 + (lane & 3) * 2;
                if (v0) {
                    float* p = out + (size_t)t0 * HH + col;
                    atomicAdd(p + 0, acc[i][jj][0] * w0);
                    atomicAdd(p + 1, acc[i][jj][1] * w0);
                }
                if (v1) {
                    float* p = out + (size_t)t1 * HH + col;
                    atomicAdd(p + 0, acc[i][jj][2] * w1);
                    atomicAdd(p + 1, acc[i][jj][3] * w1);
                }
            }
        }
    }
}

// ---------------- launch ----------------
extern "C" void kernel_launch(void* const* d_in, const int* in_sizes, int n_in,
                              void* d_out, int out_size) {
    const float* x     = (const float*)d_in[0];
    const float* Wgate = (const float*)d_in[1];
    const float* Wg    = (const float*)d_in[2];
    const float* Wu    = (const float*)d_in[3];
    const float* Wd    = (const float*)d_in[4];
    float* out = (float*)d_out;

    const int SMEM = 2 * (BM + 2 * BN) * ASTR * 2;  // 73728 B (same for both roles)

    static void* p_cnt = nullptr;
    static void* p_rdy = nullptr;
    if (!p_cnt) {
        cudaFuncSetAttribute(moe_fused, cudaFuncAttributeMaxDynamicSharedMemorySize, SMEM);
        cudaGetSymbolAddress(&p_cnt, g_cnt);
        cudaGetSymbolAddress(&p_rdy, g_rdy);
    }

    cudaMemsetAsync(out, 0, (size_t)TT * HH * sizeof(float));
    cudaMemsetAsync(p_cnt, 0, NE * sizeof(int));
    cudaMemsetAsync(p_rdy, 0, NE * NMB * sizeof(int));
    router_gather<<<TT / 8, 256>>>(x, Wgate);
    moe_fused<<<NE * SEG, 256, SMEM>>>(Wg, Wu, Wd, out);
}